// round 8
// baseline (speedup 1.0000x reference)
#include <cuda_runtime.h>
#include <cuda_fp16.h>
#include <cstdint>

#define BB    32
#define NN    1024
#define ND    14
#define HID   64
#define HEADD 128
#define MAXN  64
#define ROWS  (BB*NN)          // 32768
#define RPB   64               // rows per block in agg kernels
#define NBLK  (ROWS/RPB)       // 512
#define PAD   66               // padded h-row stride (floats)

typedef unsigned long long ull;

#define FMA2(d, a, b, c) \
    asm("fma.rn.f32x2 %0, %1, %2, %3;" : "=l"(d) : "l"(a), "l"(b), "l"(c))
#define DUP2(d, s) \
    asm("mov.b64 %0, {%1, %1};" : "=l"(d) : "f"(s))
#define UNPACK2(lo, hi, s) \
    asm("mov.b64 {%0, %1}, %2;" : "=f"(lo), "=f"(hi) : "l"(s))

// ---------------- scratch (device globals; no allocations) ----------------
__device__ unsigned short g_nbr[ROWS * MAXN];   // ELL neighbor lists
__device__ int   g_cnt[ROWS];
__device__ float g_dinv[ROWS];
__device__ __half2 g_bufA[ROWS * HID / 2];      // fp16 activations
__device__ __half2 g_bufB[ROWS * HID / 2];
__device__ float g_pool[NBLK * HID];            // per-block pool partials (fp32)

// ---------------------------------------------------------------------------
// K1: 2 rows per warp, interleaved loads + interleaved warp-scans (2 indep
// serial chains -> 2x ILP on the scan). uint16 ELL + dinv. 128MB read once.
// ---------------------------------------------------------------------------
__global__ void __launch_bounds__(256) k_adj(const float4* __restrict__ adj4) {
    int tid  = threadIdx.x;
    int w    = tid >> 5;
    int lane = tid & 31;
    int pair = blockIdx.x * 8 + w;                 // warp handles rows 2p, 2p+1
    int row0 = pair * 2, row1 = row0 + 1;

    const float4* rp0 = adj4 + (size_t)row0 * (NN / 4);
    const float4* rp1 = adj4 + (size_t)row1 * (NN / 4);
    int base0 = row0 * MAXN, base1 = row1 * MAXN;
    int cnt0 = 0, cnt1 = 0;

    #pragma unroll
    for (int h = 0; h < 2; ++h) {
        float4 va[4], vb[4];
        #pragma unroll
        for (int k = 0; k < 4; ++k) {
            va[k] = rp0[(h * 4 + k) * 32 + lane];
            vb[k] = rp1[(h * 4 + k) * 32 + lane];
        }
        #pragma unroll
        for (int k = 0; k < 4; ++k) {
            int col0 = ((h * 4 + k) * 32 + lane) * 4;
            int m0 = (va[k].x != 0.f ? 1 : 0) | (va[k].y != 0.f ? 2 : 0)
                   | (va[k].z != 0.f ? 4 : 0) | (va[k].w != 0.f ? 8 : 0);
            int m1 = (vb[k].x != 0.f ? 1 : 0) | (vb[k].y != 0.f ? 2 : 0)
                   | (vb[k].z != 0.f ? 4 : 0) | (vb[k].w != 0.f ? 8 : 0);
            int c0 = __popc(m0), c1 = __popc(m1);
            int x0 = c0, x1 = c1;
            #pragma unroll
            for (int d = 1; d < 32; d <<= 1) {
                int y0 = __shfl_up_sync(0xffffffffu, x0, d);
                int y1 = __shfl_up_sync(0xffffffffu, x1, d);
                if (lane >= d) { x0 += y0; x1 += y1; }
            }
            int w0 = cnt0 + x0 - c0;
            int w1 = cnt1 + x1 - c1;
            int t0 = __shfl_sync(0xffffffffu, x0, 31);
            int t1 = __shfl_sync(0xffffffffu, x1, 31);
            if (m0 & 1) { if (w0 < MAXN) g_nbr[base0 + w0] = (unsigned short)col0;       w0++; }
            if (m0 & 2) { if (w0 < MAXN) g_nbr[base0 + w0] = (unsigned short)(col0 + 1); w0++; }
            if (m0 & 4) { if (w0 < MAXN) g_nbr[base0 + w0] = (unsigned short)(col0 + 2); w0++; }
            if (m0 & 8) { if (w0 < MAXN) g_nbr[base0 + w0] = (unsigned short)(col0 + 3); w0++; }
            if (m1 & 1) { if (w1 < MAXN) g_nbr[base1 + w1] = (unsigned short)col0;       w1++; }
            if (m1 & 2) { if (w1 < MAXN) g_nbr[base1 + w1] = (unsigned short)(col0 + 1); w1++; }
            if (m1 & 4) { if (w1 < MAXN) g_nbr[base1 + w1] = (unsigned short)(col0 + 2); w1++; }
            if (m1 & 8) { if (w1 < MAXN) g_nbr[base1 + w1] = (unsigned short)(col0 + 3); w1++; }
            cnt0 += t0; cnt1 += t1;
        }
    }
    if (lane == 0) {
        g_cnt[row0]  = cnt0;
        g_dinv[row0] = rsqrtf((float)(cnt0 > 0 ? cnt0 : 1));
        g_cnt[row1]  = cnt1;
        g_dinv[row1] = rsqrtf((float)(cnt1 > 0 ? cnt1 : 1));
    }
}

// ---------------------------------------------------------------------------
// K2: z0[row] = dinv[row] * (x[row] @ W1), output fp16. 64 rows / 256-thr
// block; 8 groups of 32 lanes, lane = channel pair, 8 rows per group.
// ---------------------------------------------------------------------------
__global__ void __launch_bounds__(256) k_lin0(const float* __restrict__ x,
                                              const float* __restrict__ W1,
                                              __half2* __restrict__ out) {
    int tid  = threadIdx.x;
    int g    = tid >> 5;
    int lane = tid & 31;
    int R0   = blockIdx.x * 64;

    __shared__ float sx[64 * ND];
    __shared__ float sdinv[64];

    float2 wreg[ND];
    #pragma unroll
    for (int c = 0; c < ND; ++c)
        wreg[c] = ((const float2*)(W1 + c * HID))[lane];

    for (int i = tid; i < 64 * ND; i += 256) sx[i] = x[(size_t)R0 * ND + i];
    if (tid < 64) sdinv[tid] = g_dinv[R0 + tid];
    __syncthreads();

    #pragma unroll
    for (int rr = 0; rr < 8; ++rr) {
        int r = g * 8 + rr;
        const float* xr = sx + r * ND;
        float ax = 0.f, ay = 0.f;
        #pragma unroll
        for (int c = 0; c < ND; ++c) {
            ax = fmaf(xr[c], wreg[c].x, ax);
            ay = fmaf(xr[c], wreg[c].y, ay);
        }
        float di = sdinv[r];
        out[(size_t)(R0 + r) * (HID / 2) + lane] = __floats2half2_rn(ax * di, ay * di);
    }
}

// ---------------------------------------------------------------------------
// K3: fused aggregation layer, 64 rows / 256-thread block (R5 structure).
//  Phase 1: warp w = rows w*8..w*8+7 interleaved; lane = channel pair;
//           fp16 gather (LDG.32) + fp32 accumulate. relu -> padded smem
//           (HAS_MV) or fp32 pool partial (!HAS_MV).
//  Phase 2 (HAS_MV): 64x64x64 micro-GEMM, thread tile 4 rows x 4 cols,
//           packed FMA2; output packed to fp16.
// ---------------------------------------------------------------------------
template <int HAS_MV>
__global__ void __launch_bounds__(256) k_agg(const __half2* __restrict__ zin,
                                             const float* __restrict__ bias,
                                             const float* __restrict__ Wnext,
                                             void* __restrict__ outv) {
    int tid  = threadIdx.x;
    int w    = tid >> 5;
    int lane = tid & 31;
    int R0   = blockIdx.x * RPB;
    int bbase = (R0 >> 10) << 10;                 // batch * N

    __shared__ unsigned short sidx[RPB * MAXN];   // 8 KB
    __shared__ float sh[HAS_MV ? RPB * PAD : 1];  // 16.9 KB
    __shared__ float sW[HAS_MV ? HID * HID : 1];  // 16 KB
    __shared__ float sdinv[RPB];
    __shared__ int   scnt[RPB];
    __shared__ float2 spart[8][32];

    // ---- stage: ELL lists (int4), W (float4), dinv, cnt ----
    {
        const int4* src = (const int4*)(g_nbr + (size_t)R0 * MAXN);
        int4* dst = (int4*)sidx;
        #pragma unroll
        for (int i = 0; i < RPB * MAXN * 2 / 16 / 256; ++i)   // 2 iters
            dst[tid + i * 256] = src[tid + i * 256];
        if (HAS_MV) {
            const float4* ws = (const float4*)Wnext;
            float4* wd = (float4*)sW;
            #pragma unroll
            for (int i = 0; i < HID * HID / 4 / 256; ++i)     // 4 iters
                wd[tid + i * 256] = ws[tid + i * 256];
        }
        if (tid < RPB) {
            int c = g_cnt[R0 + tid];
            scnt[tid]  = c > MAXN ? MAXN : c;
            sdinv[tid] = g_dinv[R0 + tid];
        }
    }
    __syncthreads();

    // ---- phase 1: 8 rows per warp, interleaved fp16 gather, fp32 acc ----
    {
        const float2 bf = ((const float2*)bias)[lane];
        const __half2* zb = zin + (size_t)bbase * (HID / 2) + lane;

        int r0 = w * 8;
        int cn[8];
        const unsigned short* ip[8];
        float ax[8], ay[8];
        #pragma unroll
        for (int i = 0; i < 8; ++i) {
            cn[i] = scnt[r0 + i];
            ip[i] = sidx + (r0 + i) * MAXN;
            ax[i] = 0.f; ay[i] = 0.f;
        }
        int cmax = 0;
        #pragma unroll
        for (int i = 0; i < 8; ++i) cmax = max(cmax, cn[i]);

        for (int k = 0; k < cmax; ++k) {
            #pragma unroll
            for (int i = 0; i < 8; ++i) {
                if (k < cn[i]) {
                    float2 v = __half22float2(zb[ip[i][k] * (HID / 2)]);
                    ax[i] += v.x; ay[i] += v.y;
                }
            }
        }

        float2 pacc = make_float2(0.f, 0.f);
        #pragma unroll
        for (int i = 0; i < 8; ++i) {
            float di = sdinv[r0 + i];
            float hx = fmaxf(fmaf(di, ax[i], bf.x), 0.f);
            float hy = fmaxf(fmaf(di, ay[i], bf.y), 0.f);
            if (HAS_MV) {
                *(float2*)(sh + (r0 + i) * PAD + 2 * lane) = make_float2(hx, hy);
            } else {
                pacc.x += hx; pacc.y += hy;
            }
        }

        if (!HAS_MV) {
            spart[w][lane] = pacc;
            __syncthreads();
            if (tid < 32) {
                float2 s = spart[0][tid];
                #pragma unroll
                for (int i = 1; i < 8; ++i) { s.x += spart[i][tid].x; s.y += spart[i][tid].y; }
                float* outp = (float*)outv;
                *(float2*)(outp + blockIdx.x * HID + 2 * tid) = s;
            }
            return;
        }
    }

    __syncthreads();

    // ---- phase 2: 64x64x64 micro-GEMM, 4 rows x 4 cols per thread, FMA2 ----
    {
        int tx = tid & 15;          // cols 4*tx .. 4*tx+3
        int ty = tid >> 4;          // rows 4*ty .. 4*ty+3
        __half2* outp = (__half2*)outv;

        ull acc[4][2];
        #pragma unroll
        for (int i = 0; i < 4; ++i) { acc[i][0] = 0ull; acc[i][1] = 0ull; }

        const float* shb = sh + (4 * ty) * PAD;
        #pragma unroll 4
        for (int c = 0; c < HID; ++c) {
            ulonglong2 wv = *(const ulonglong2*)(sW + c * HID + 4 * tx);
            #pragma unroll
            for (int i = 0; i < 4; ++i) {
                float hv = shb[i * PAD + c];
                ull hh; DUP2(hh, hv);
                FMA2(acc[i][0], hh, wv.x, acc[i][0]);
                FMA2(acc[i][1], hh, wv.y, acc[i][1]);
            }
        }

        #pragma unroll
        for (int i = 0; i < 4; ++i) {
            int r = 4 * ty + i;
            float di = sdinv[r];
            float a0, a1, a2, a3;
            UNPACK2(a0, a1, acc[i][0]);
            UNPACK2(a2, a3, acc[i][1]);
            __half2* op = outp + (size_t)(R0 + r) * (HID / 2) + 2 * tx;
            op[0] = __floats2half2_rn(di * a0, di * a1);
            op[1] = __floats2half2_rn(di * a2, di * a3);
        }
    }
}

// ---------------------------------------------------------------------------
// K4: per batch: pooled = mean of 16 block partials; relu(pooled@Wf1+bf1)@Wf2+bf2
// ---------------------------------------------------------------------------
__global__ void k_final(const float* __restrict__ pool,
                        const float* __restrict__ Wf1, const float* __restrict__ bf1,
                        const float* __restrict__ Wf2, const float* __restrict__ bf2,
                        float* __restrict__ out) {
    int b   = blockIdx.x;
    int tid = threadIdx.x;           // 128 threads
    __shared__ float pooled[HID];
    __shared__ float hred[HEADD];

    if (tid < HID) {
        float s = 0.f;
        #pragma unroll
        for (int i = 0; i < NN / RPB; ++i)
            s += pool[(b * (NN / RPB) + i) * HID + tid];
        pooled[tid] = s * (1.f / NN);
    }
    __syncthreads();

    float a = bf1[tid];
    #pragma unroll
    for (int c = 0; c < HID; ++c) a = fmaf(pooled[c], Wf1[c * HEADD + tid], a);
    hred[tid] = fmaxf(a, 0.f) * Wf2[tid];
    __syncthreads();

    if (tid < 32) {
        float s = hred[tid] + hred[tid + 32] + hred[tid + 64] + hred[tid + 96];
        #pragma unroll
        for (int d = 16; d; d >>= 1) s += __shfl_down_sync(0xffffffffu, s, d);
        if (tid == 0) out[b] = s + bf2[0];
    }
}

// ---------------------------------------------------------------------------
extern "C" void kernel_launch(void* const* d_in, const int* in_sizes, int n_in,
                              void* d_out, int out_size) {
    const float* x    = (const float*)d_in[0];
    const float* adj  = (const float*)d_in[1];
    const float* W1   = (const float*)d_in[2];
    const float* b1   = (const float*)d_in[3];
    const float* W2   = (const float*)d_in[4];
    const float* b2   = (const float*)d_in[5];
    const float* W3   = (const float*)d_in[6];
    const float* b3   = (const float*)d_in[7];
    const float* Wf1  = (const float*)d_in[8];
    const float* bf1  = (const float*)d_in[9];
    const float* Wf2  = (const float*)d_in[10];
    const float* bf2  = (const float*)d_in[11];
    float* out = (float*)d_out;

    __half2 *bufA, *bufB;
    float *pool;
    cudaGetSymbolAddress((void**)&bufA, g_bufA);
    cudaGetSymbolAddress((void**)&bufB, g_bufB);
    cudaGetSymbolAddress((void**)&pool, g_pool);

    k_adj<<<ROWS / 16, 256>>>((const float4*)adj);               // ELL + dinv
    k_lin0<<<ROWS / 64, 256>>>(x, W1, bufA);                     // z0 -> A (fp16)
    k_agg<1><<<NBLK, 256>>>(bufA, b1, W2, bufB);                 // layer1 -> B
    k_agg<1><<<NBLK, 256>>>(bufB, b2, W3, bufA);                 // layer2 -> A
    k_agg<0><<<NBLK, 256>>>(bufA, b3, nullptr, pool);            // layer3 -> pool
    k_final<<<BB, HEADD>>>(pool, Wf1, bf1, Wf2, bf2, out);       // head
}

// round 9
// speedup vs baseline: 1.5814x; 1.5814x over previous
#include <cuda_runtime.h>
#include <cstdint>

#define BB    32
#define NN    1024
#define ND    14
#define HID   64
#define HEADD 128
#define MAXN  64
#define ROWS  (BB*NN)          // 32768
#define RPB   32               // rows per block in agg kernels
#define NBLK  (ROWS/RPB)       // 1024
#define PAD   66               // padded h-row stride (floats)

typedef unsigned long long ull;

#define FMA2(d, a, b, c) \
    asm("fma.rn.f32x2 %0, %1, %2, %3;" : "=l"(d) : "l"(a), "l"(b), "l"(c))
#define ADD2(d, a, b) \
    asm("add.rn.f32x2 %0, %1, %2;" : "=l"(d) : "l"(a), "l"(b))
#define DUP2(d, s) \
    asm("mov.b64 %0, {%1, %1};" : "=l"(d) : "f"(s))
#define UNPACK2(lo, hi, s) \
    asm("mov.b64 {%0, %1}, %2;" : "=f"(lo), "=f"(hi) : "l"(s))

// ---------------- scratch (device globals; no allocations) ----------------
__device__ unsigned short g_nbr[ROWS * MAXN];   // ELL neighbor lists
__device__ int   g_cnt[ROWS];
__device__ float g_dinv[ROWS];
__device__ float g_bufA[ROWS * HID];
__device__ float g_bufB[ROWS * HID];
__device__ float g_pool[NBLK * HID];            // per-block pool partials

// ---------------------------------------------------------------------------
// K1: one warp per adjacency row; 8 float4 loads up-front, then BALLOT-based
// nonzero extraction (no serial scan chain; ELL order is irrelevant for sums).
// 128MB read once -> HBM-bound.
// ---------------------------------------------------------------------------
__global__ void k_adj(const float4* __restrict__ adj4) {
    int gtid = blockIdx.x * blockDim.x + threadIdx.x;
    int row  = gtid >> 5;
    int lane = gtid & 31;
    if (row >= ROWS) return;

    const float4* rp = adj4 + (size_t)row * (NN / 4);
    float4 v[8];
    #pragma unroll
    for (int k = 0; k < 8; ++k) v[k] = rp[k * 32 + lane];

    int base = row * MAXN;
    unsigned lt = (1u << lane) - 1u;
    int cnt = 0;
    #pragma unroll
    for (int k = 0; k < 8; ++k) {
        int colb = (k * 32 + lane) * 4;
        bool px = v[k].x != 0.f, py = v[k].y != 0.f;
        bool pz = v[k].z != 0.f, pw = v[k].w != 0.f;
        unsigned b0 = __ballot_sync(0xffffffffu, px);
        unsigned b1 = __ballot_sync(0xffffffffu, py);
        unsigned b2 = __ballot_sync(0xffffffffu, pz);
        unsigned b3 = __ballot_sync(0xffffffffu, pw);
        int p0 = __popc(b0), p1 = __popc(b1), p2 = __popc(b2), p3 = __popc(b3);
        int o0 = cnt + __popc(b0 & lt);
        int o1 = cnt + p0 + __popc(b1 & lt);
        int o2 = cnt + p0 + p1 + __popc(b2 & lt);
        int o3 = cnt + p0 + p1 + p2 + __popc(b3 & lt);
        if (px && o0 < MAXN) g_nbr[base + o0] = (unsigned short)(colb);
        if (py && o1 < MAXN) g_nbr[base + o1] = (unsigned short)(colb + 1);
        if (pz && o2 < MAXN) g_nbr[base + o2] = (unsigned short)(colb + 2);
        if (pw && o3 < MAXN) g_nbr[base + o3] = (unsigned short)(colb + 3);
        cnt += p0 + p1 + p2 + p3;
    }
    if (lane == 0) {
        g_cnt[row]  = cnt;
        g_dinv[row] = rsqrtf((float)(cnt > 0 ? cnt : 1));
    }
}

// ---------------------------------------------------------------------------
// K2: z0[row] = dinv[row] * (x[row] @ W1). 64 rows / 256-thread block.
// ---------------------------------------------------------------------------
__global__ void __launch_bounds__(256) k_lin0(const float* __restrict__ x,
                                              const float* __restrict__ W1,
                                              float* __restrict__ out) {
    int tid = threadIdx.x;
    int g   = tid >> 6;
    int t   = tid & 63;
    int R0  = blockIdx.x * 64;

    __shared__ float sx[64 * ND];
    __shared__ float sdinv[64];

    float wreg[ND];
    #pragma unroll
    for (int c = 0; c < ND; ++c) wreg[c] = W1[c * HID + t];

    for (int i = tid; i < 64 * ND; i += 256) sx[i] = x[(size_t)R0 * ND + i];
    if (tid < 64) sdinv[tid] = g_dinv[R0 + tid];
    __syncthreads();

    #pragma unroll 4
    for (int rr = 0; rr < 16; ++rr) {
        int r = g * 16 + rr;
        const float* xr = sx + r * ND;
        float a = 0.f;
        #pragma unroll
        for (int c = 0; c < ND; ++c) a = fmaf(xr[c], wreg[c], a);
        out[(size_t)(R0 + r) * HID + t] = a * sdinv[r];
    }
}

// ---------------------------------------------------------------------------
// K3: fused aggregation layer, 32 rows / 128-thread block (grid 1024).
//  Phase 1: warp w = rows w*8..w*8+7 interleaved; lane = channel pair;
//           LDG.64 gather, packed add.rn.f32x2.  h = relu(dinv*agg + b)
//           -> padded smem (HAS_MV) or pool partial (!HAS_MV).
//  Phase 2 (HAS_MV): 32x64x64 micro-GEMM, thread tile 4 rows x 4 cols,
//           packed FMA2 (exact R5 per-thread shape).
// ---------------------------------------------------------------------------
template <int HAS_MV>
__global__ void __launch_bounds__(128) k_agg(const float* __restrict__ zin,
                                             const float* __restrict__ bias,
                                             const float* __restrict__ Wnext,
                                             float* __restrict__ out) {
    int tid  = threadIdx.x;
    int w    = tid >> 5;
    int lane = tid & 31;
    int R0   = blockIdx.x * RPB;
    int bbase = (R0 >> 10) << 10;                 // batch * N

    __shared__ unsigned short sidx[RPB * MAXN];   // 4 KB
    __shared__ float sh[HAS_MV ? RPB * PAD : 1];  // 8.25 KB
    __shared__ float sW[HAS_MV ? HID * HID : 1];  // 16 KB
    __shared__ float sdinv[RPB];
    __shared__ int   scnt[RPB];
    __shared__ float2 spart[4][32];

    // ---- stage: ELL lists (int4), W (float4), dinv, cnt ----
    {
        const int4* src = (const int4*)(g_nbr + (size_t)R0 * MAXN);
        int4* dst = (int4*)sidx;
        dst[tid]       = src[tid];
        dst[tid + 128] = src[tid + 128];
        if (HAS_MV) {
            const float4* ws = (const float4*)Wnext;
            float4* wd = (float4*)sW;
            #pragma unroll
            for (int i = 0; i < 8; ++i)
                wd[tid + i * 128] = ws[tid + i * 128];
        }
        if (tid < RPB) {
            int c = g_cnt[R0 + tid];
            scnt[tid]  = c > MAXN ? MAXN : c;
            sdinv[tid] = g_dinv[R0 + tid];
        }
    }
    __syncthreads();

    // ---- phase 1: 8 rows per warp, interleaved gather, packed adds ----
    {
        const float2 bf = ((const float2*)bias)[lane];
        const ull* zb = (const ull*)zin + (size_t)bbase * (HID / 2) + lane;

        int r0 = w * 8;
        int cn[8];
        const unsigned short* ip[8];
        ull acc[8];
        #pragma unroll
        for (int i = 0; i < 8; ++i) {
            cn[i]  = scnt[r0 + i];
            ip[i]  = sidx + (r0 + i) * MAXN;
            acc[i] = 0ull;
        }
        int cmax = 0;
        #pragma unroll
        for (int i = 0; i < 8; ++i) cmax = max(cmax, cn[i]);

        for (int k = 0; k < cmax; ++k) {
            #pragma unroll
            for (int i = 0; i < 8; ++i) {
                if (k < cn[i]) {
                    ull v = zb[ip[i][k] * (HID / 2)];
                    ADD2(acc[i], acc[i], v);
                }
            }
        }

        float2 pacc = make_float2(0.f, 0.f);
        #pragma unroll
        for (int i = 0; i < 8; ++i) {
            float ax, ay;
            UNPACK2(ax, ay, acc[i]);
            float di = sdinv[r0 + i];
            float hx = fmaxf(fmaf(di, ax, bf.x), 0.f);
            float hy = fmaxf(fmaf(di, ay, bf.y), 0.f);
            if (HAS_MV) {
                *(float2*)(sh + (r0 + i) * PAD + 2 * lane) = make_float2(hx, hy);
            } else {
                pacc.x += hx; pacc.y += hy;
            }
        }

        if (!HAS_MV) {
            spart[w][lane] = pacc;
            __syncthreads();
            if (tid < 32) {
                float2 s = spart[0][tid];
                #pragma unroll
                for (int i = 1; i < 4; ++i) { s.x += spart[i][tid].x; s.y += spart[i][tid].y; }
                *(float2*)(out + blockIdx.x * HID + 2 * tid) = s;
            }
            return;
        }
    }

    __syncthreads();

    // ---- phase 2: 32x64x64 micro-GEMM, 4 rows x 4 cols per thread, FMA2 ----
    {
        int tx = tid & 15;          // cols 4*tx .. 4*tx+3
        int ty = tid >> 4;          // rows 4*ty .. 4*ty+3 (ty in 0..7 -> 32 rows)

        ull acc[4][2];
        #pragma unroll
        for (int i = 0; i < 4; ++i) { acc[i][0] = 0ull; acc[i][1] = 0ull; }

        const float* shb = sh + (4 * ty) * PAD;
        #pragma unroll 4
        for (int c = 0; c < HID; ++c) {
            ulonglong2 wv = *(const ulonglong2*)(sW + c * HID + 4 * tx);
            #pragma unroll
            for (int i = 0; i < 4; ++i) {
                float hv = shb[i * PAD + c];
                ull hh; DUP2(hh, hv);
                FMA2(acc[i][0], hh, wv.x, acc[i][0]);
                FMA2(acc[i][1], hh, wv.y, acc[i][1]);
            }
        }

        #pragma unroll
        for (int i = 0; i < 4; ++i) {
            int r = 4 * ty + i;
            float di = sdinv[r];
            float a0, a1, a2, a3;
            UNPACK2(a0, a1, acc[i][0]);
            UNPACK2(a2, a3, acc[i][1]);
            float4 o;
            o.x = di * a0; o.y = di * a1; o.z = di * a2; o.w = di * a3;
            *(float4*)(out + (size_t)(R0 + r) * HID + 4 * tx) = o;
        }
    }
}

// ---------------------------------------------------------------------------
// K4: per batch: pooled = mean of 32 block partials; relu(pooled@Wf1+bf1)@Wf2+bf2
// ---------------------------------------------------------------------------
__global__ void k_final(const float* __restrict__ pool,
                        const float* __restrict__ Wf1, const float* __restrict__ bf1,
                        const float* __restrict__ Wf2, const float* __restrict__ bf2,
                        float* __restrict__ out) {
    int b   = blockIdx.x;
    int tid = threadIdx.x;           // 128 threads
    __shared__ float pooled[HID];
    __shared__ float hred[HEADD];

    if (tid < HID) {
        float s = 0.f;
        #pragma unroll
        for (int i = 0; i < NN / RPB; ++i)
            s += pool[(b * (NN / RPB) + i) * HID + tid];
        pooled[tid] = s * (1.f / NN);
    }
    __syncthreads();

    float a = bf1[tid];
    #pragma unroll
    for (int c = 0; c < HID; ++c) a = fmaf(pooled[c], Wf1[c * HEADD + tid], a);
    hred[tid] = fmaxf(a, 0.f) * Wf2[tid];
    __syncthreads();

    if (tid < 32) {
        float s = hred[tid] + hred[tid + 32] + hred[tid + 64] + hred[tid + 96];
        #pragma unroll
        for (int d = 16; d; d >>= 1) s += __shfl_down_sync(0xffffffffu, s, d);
        if (tid == 0) out[b] = s + bf2[0];
    }
}

// ---------------------------------------------------------------------------
extern "C" void kernel_launch(void* const* d_in, const int* in_sizes, int n_in,
                              void* d_out, int out_size) {
    const float* x    = (const float*)d_in[0];
    const float* adj  = (const float*)d_in[1];
    const float* W1   = (const float*)d_in[2];
    const float* b1   = (const float*)d_in[3];
    const float* W2   = (const float*)d_in[4];
    const float* b2   = (const float*)d_in[5];
    const float* W3   = (const float*)d_in[6];
    const float* b3   = (const float*)d_in[7];
    const float* Wf1  = (const float*)d_in[8];
    const float* bf1  = (const float*)d_in[9];
    const float* Wf2  = (const float*)d_in[10];
    const float* bf2  = (const float*)d_in[11];
    float* out = (float*)d_out;

    float *bufA, *bufB, *pool;
    cudaGetSymbolAddress((void**)&bufA, g_bufA);
    cudaGetSymbolAddress((void**)&bufB, g_bufB);
    cudaGetSymbolAddress((void**)&pool, g_pool);

    k_adj<<<ROWS * 32 / 256, 256>>>((const float4*)adj);         // ELL + dinv
    k_lin0<<<ROWS / 64, 256>>>(x, W1, bufA);                     // z0 -> A
    k_agg<1><<<NBLK, 128>>>(bufA, b1, W2, bufB);                 // layer1 -> B
    k_agg<1><<<NBLK, 128>>>(bufB, b2, W3, bufA);                 // layer2 -> A
    k_agg<0><<<NBLK, 128>>>(bufA, b3, nullptr, pool);            // layer3 -> pool
    k_final<<<BB, HEADD>>>(pool, Wf1, bf1, Wf2, bf2, out);       // head
}

// round 10
// speedup vs baseline: 1.6157x; 1.0217x over previous
#include <cuda_runtime.h>
#include <cstdint>

#define BB    32
#define NN    1024
#define ND    14
#define HID   64
#define HEADD 128
#define MAXN  64
#define ROWS  (BB*NN)          // 32768
#define RPB   32               // rows per block in agg kernels
#define NBLK  (ROWS/RPB)       // 1024
#define PAD   66               // padded h-row stride (floats)
#define WPAD  68               // padded W row stride (float4-aligned)

typedef unsigned long long ull;

#define ADD2(d, a, b) \
    asm("add.rn.f32x2 %0, %1, %2;" : "=l"(d) : "l"(a), "l"(b))
#define UNPACK2(lo, hi, s) \
    asm("mov.b64 {%0, %1}, %2;" : "=f"(lo), "=f"(hi) : "l"(s))

__device__ __forceinline__ uint32_t cvt_tf32(float x) {
    uint32_t r;
    asm("cvt.rna.tf32.f32 %0, %1;" : "=r"(r) : "f"(x));
    return r;
}

// ---------------- scratch (device globals; no allocations) ----------------
__device__ unsigned short g_nbr[ROWS * MAXN];   // ELL neighbor lists
__device__ int   g_cnt[ROWS];
__device__ float g_dinv[ROWS];
__device__ float g_bufA[ROWS * HID];
__device__ float g_bufB[ROWS * HID];
__device__ float g_pool[NBLK * HID];            // per-block pool partials

// ---------------------------------------------------------------------------
// K1: one warp per adjacency row; 8 float4 loads up-front, ballot-based
// nonzero extraction. uint16 ELL + dinv. 128MB read once -> HBM-bound.
// ---------------------------------------------------------------------------
__global__ void k_adj(const float4* __restrict__ adj4) {
    int gtid = blockIdx.x * blockDim.x + threadIdx.x;
    int row  = gtid >> 5;
    int lane = gtid & 31;
    if (row >= ROWS) return;

    const float4* rp = adj4 + (size_t)row * (NN / 4);
    float4 v[8];
    #pragma unroll
    for (int k = 0; k < 8; ++k) v[k] = rp[k * 32 + lane];

    int base = row * MAXN;
    unsigned lt = (1u << lane) - 1u;
    int cnt = 0;
    #pragma unroll
    for (int k = 0; k < 8; ++k) {
        int colb = (k * 32 + lane) * 4;
        bool px = v[k].x != 0.f, py = v[k].y != 0.f;
        bool pz = v[k].z != 0.f, pw = v[k].w != 0.f;
        unsigned b0 = __ballot_sync(0xffffffffu, px);
        unsigned b1 = __ballot_sync(0xffffffffu, py);
        unsigned b2 = __ballot_sync(0xffffffffu, pz);
        unsigned b3 = __ballot_sync(0xffffffffu, pw);
        int p0 = __popc(b0), p1 = __popc(b1), p2 = __popc(b2), p3 = __popc(b3);
        int o0 = cnt + __popc(b0 & lt);
        int o1 = cnt + p0 + __popc(b1 & lt);
        int o2 = cnt + p0 + p1 + __popc(b2 & lt);
        int o3 = cnt + p0 + p1 + p2 + __popc(b3 & lt);
        if (px && o0 < MAXN) g_nbr[base + o0] = (unsigned short)(colb);
        if (py && o1 < MAXN) g_nbr[base + o1] = (unsigned short)(colb + 1);
        if (pz && o2 < MAXN) g_nbr[base + o2] = (unsigned short)(colb + 2);
        if (pw && o3 < MAXN) g_nbr[base + o3] = (unsigned short)(colb + 3);
        cnt += p0 + p1 + p2 + p3;
    }
    if (lane == 0) {
        g_cnt[row]  = cnt;
        g_dinv[row] = rsqrtf((float)(cnt > 0 ? cnt : 1));
    }
}

// ---------------------------------------------------------------------------
// K2: z0[row] = dinv[row] * (x[row] @ W1). 64 rows / 256-thread block.
// ---------------------------------------------------------------------------
__global__ void __launch_bounds__(256) k_lin0(const float* __restrict__ x,
                                              const float* __restrict__ W1,
                                              float* __restrict__ out) {
    int tid = threadIdx.x;
    int g   = tid >> 6;
    int t   = tid & 63;
    int R0  = blockIdx.x * 64;

    __shared__ float sx[64 * ND];
    __shared__ float sdinv[64];

    float wreg[ND];
    #pragma unroll
    for (int c = 0; c < ND; ++c) wreg[c] = W1[c * HID + t];

    for (int i = tid; i < 64 * ND; i += 256) sx[i] = x[(size_t)R0 * ND + i];
    if (tid < 64) sdinv[tid] = g_dinv[R0 + tid];
    __syncthreads();

    #pragma unroll 4
    for (int rr = 0; rr < 16; ++rr) {
        int r = g * 16 + rr;
        const float* xr = sx + r * ND;
        float a = 0.f;
        #pragma unroll
        for (int c = 0; c < ND; ++c) a = fmaf(xr[c], wreg[c], a);
        out[(size_t)(R0 + r) * HID + t] = a * sdinv[r];
    }
}

// ---------------------------------------------------------------------------
// K3: fused aggregation layer, 32 rows / 128-thread block (grid 1024).
//  Phase 1: warp w = rows w*8..w*8+7 interleaved; lane = channel pair;
//           LDG.64 gather, packed add.rn.f32x2. h = relu(dinv*agg + b)
//           -> padded smem (HAS_MV) or pool partial (!HAS_MV).
//  Phase 2 (HAS_MV): 32x64x64 GEMM via tf32 mma.sync.m16n8k8.
//           Warp w: rows (w&1)*16..+15, cols (w>>1)*32..+31 -> 32 HMMA/warp.
// ---------------------------------------------------------------------------
template <int HAS_MV>
__global__ void __launch_bounds__(128) k_agg(const float* __restrict__ zin,
                                             const float* __restrict__ bias,
                                             const float* __restrict__ Wnext,
                                             float* __restrict__ out) {
    int tid  = threadIdx.x;
    int w    = tid >> 5;
    int lane = tid & 31;
    int R0   = blockIdx.x * RPB;
    int bbase = (R0 >> 10) << 10;                 // batch * N

    __shared__ unsigned short sidx[RPB * MAXN];   // 4 KB
    __shared__ float sh[HAS_MV ? RPB * PAD : 1];  // 8.25 KB
    __shared__ float sW[HAS_MV ? HID * WPAD : 1]; // 17 KB (padded rows)
    __shared__ float sdinv[RPB];
    __shared__ int   scnt[RPB];
    __shared__ float2 spart[4][32];

    // ---- stage: ELL lists (int4), W (padded float4), dinv, cnt ----
    {
        const int4* src = (const int4*)(g_nbr + (size_t)R0 * MAXN);
        int4* dst = (int4*)sidx;
        dst[tid]       = src[tid];
        dst[tid + 128] = src[tid + 128];
        if (HAS_MV) {
            const float4* ws = (const float4*)Wnext;
            #pragma unroll
            for (int i = 0; i < 8; ++i) {
                int f   = tid + i * 128;          // 0..1023
                float4 v = ws[f];
                int row = f >> 4;
                int c4  = f & 15;
                *(float4*)(sW + row * WPAD + c4 * 4) = v;
            }
        }
        if (tid < RPB) {
            int c = g_cnt[R0 + tid];
            scnt[tid]  = c > MAXN ? MAXN : c;
            sdinv[tid] = g_dinv[R0 + tid];
        }
    }
    __syncthreads();

    // ---- phase 1: 8 rows per warp, interleaved gather, packed adds ----
    {
        const float2 bf = ((const float2*)bias)[lane];
        const ull* zb = (const ull*)zin + (size_t)bbase * (HID / 2) + lane;

        int r0 = w * 8;
        int cn[8];
        const unsigned short* ip[8];
        ull acc[8];
        #pragma unroll
        for (int i = 0; i < 8; ++i) {
            cn[i]  = scnt[r0 + i];
            ip[i]  = sidx + (r0 + i) * MAXN;
            acc[i] = 0ull;
        }
        int cmax = 0;
        #pragma unroll
        for (int i = 0; i < 8; ++i) cmax = max(cmax, cn[i]);

        for (int k = 0; k < cmax; ++k) {
            #pragma unroll
            for (int i = 0; i < 8; ++i) {
                if (k < cn[i]) {
                    ull v = zb[ip[i][k] * (HID / 2)];
                    ADD2(acc[i], acc[i], v);
                }
            }
        }

        float2 pacc = make_float2(0.f, 0.f);
        #pragma unroll
        for (int i = 0; i < 8; ++i) {
            float ax, ay;
            UNPACK2(ax, ay, acc[i]);
            float di = sdinv[r0 + i];
            float hx = fmaxf(fmaf(di, ax, bf.x), 0.f);
            float hy = fmaxf(fmaf(di, ay, bf.y), 0.f);
            if (HAS_MV) {
                *(float2*)(sh + (r0 + i) * PAD + 2 * lane) = make_float2(hx, hy);
            } else {
                pacc.x += hx; pacc.y += hy;
            }
        }

        if (!HAS_MV) {
            spart[w][lane] = pacc;
            __syncthreads();
            if (tid < 32) {
                float2 s = spart[0][tid];
                #pragma unroll
                for (int i = 1; i < 4; ++i) { s.x += spart[i][tid].x; s.y += spart[i][tid].y; }
                *(float2*)(out + blockIdx.x * HID + 2 * tid) = s;
            }
            return;
        }
    }

    __syncthreads();

    // ---- phase 2: 32x64x64 GEMM via tf32 HMMA ----
    {
        int g  = lane >> 2;                 // 0..7
        int tg = lane & 3;                  // 0..3
        int mrow = (w & 1) * 16;            // 0 or 16
        int ncol = (w >> 1) * 32;           // 0 or 32

        float c[4][4];
        #pragma unroll
        for (int j = 0; j < 4; ++j)
            #pragma unroll
            for (int i = 0; i < 4; ++i) c[j][i] = 0.f;

        #pragma unroll
        for (int k0 = 0; k0 < HID; k0 += 8) {
            uint32_t a[4];
            a[0] = cvt_tf32(sh[(mrow + g    ) * PAD + k0 + tg]);
            a[1] = cvt_tf32(sh[(mrow + g + 8) * PAD + k0 + tg]);
            a[2] = cvt_tf32(sh[(mrow + g    ) * PAD + k0 + tg + 4]);
            a[3] = cvt_tf32(sh[(mrow + g + 8) * PAD + k0 + tg + 4]);
            #pragma unroll
            for (int j = 0; j < 4; ++j) {
                int n0 = ncol + j * 8;
                uint32_t b[2];
                b[0] = cvt_tf32(sW[(k0 + tg    ) * WPAD + n0 + g]);
                b[1] = cvt_tf32(sW[(k0 + tg + 4) * WPAD + n0 + g]);
                asm volatile(
                    "mma.sync.aligned.m16n8k8.row.col.f32.tf32.tf32.f32 "
                    "{%0,%1,%2,%3},{%4,%5,%6,%7},{%8,%9},{%0,%1,%2,%3};"
                    : "+f"(c[j][0]), "+f"(c[j][1]), "+f"(c[j][2]), "+f"(c[j][3])
                    : "r"(a[0]), "r"(a[1]), "r"(a[2]), "r"(a[3]),
                      "r"(b[0]), "r"(b[1]));
            }
        }

        int r0 = mrow + g, r1 = mrow + g + 8;
        float d0 = sdinv[r0], d1 = sdinv[r1];
        #pragma unroll
        for (int j = 0; j < 4; ++j) {
            int n0 = ncol + j * 8 + 2 * tg;
            *(float2*)(out + (size_t)(R0 + r0) * HID + n0) =
                make_float2(d0 * c[j][0], d0 * c[j][1]);
            *(float2*)(out + (size_t)(R0 + r1) * HID + n0) =
                make_float2(d1 * c[j][2], d1 * c[j][3]);
        }
    }
}

// ---------------------------------------------------------------------------
// K4: per batch: pooled = mean of 32 block partials; relu(pooled@Wf1+bf1)@Wf2+bf2
// ---------------------------------------------------------------------------
__global__ void k_final(const float* __restrict__ pool,
                        const float* __restrict__ Wf1, const float* __restrict__ bf1,
                        const float* __restrict__ Wf2, const float* __restrict__ bf2,
                        float* __restrict__ out) {
    int b   = blockIdx.x;
    int tid = threadIdx.x;           // 128 threads
    __shared__ float pooled[HID];
    __shared__ float hred[HEADD];

    if (tid < HID) {
        float s = 0.f;
        #pragma unroll
        for (int i = 0; i < NN / RPB; ++i)
            s += pool[(b * (NN / RPB) + i) * HID + tid];
        pooled[tid] = s * (1.f / NN);
    }
    __syncthreads();

    float a = bf1[tid];
    #pragma unroll
    for (int c = 0; c < HID; ++c) a = fmaf(pooled[c], Wf1[c * HEADD + tid], a);
    hred[tid] = fmaxf(a, 0.f) * Wf2[tid];
    __syncthreads();

    if (tid < 32) {
        float s = hred[tid] + hred[tid + 32] + hred[tid + 64] + hred[tid + 96];
        #pragma unroll
        for (int d = 16; d; d >>= 1) s += __shfl_down_sync(0xffffffffu, s, d);
        if (tid == 0) out[b] = s + bf2[0];
    }
}

// ---------------------------------------------------------------------------
extern "C" void kernel_launch(void* const* d_in, const int* in_sizes, int n_in,
                              void* d_out, int out_size) {
    const float* x    = (const float*)d_in[0];
    const float* adj  = (const float*)d_in[1];
    const float* W1   = (const float*)d_in[2];
    const float* b1   = (const float*)d_in[3];
    const float* W2   = (const float*)d_in[4];
    const float* b2   = (const float*)d_in[5];
    const float* W3   = (const float*)d_in[6];
    const float* b3   = (const float*)d_in[7];
    const float* Wf1  = (const float*)d_in[8];
    const float* bf1  = (const float*)d_in[9];
    const float* Wf2  = (const float*)d_in[10];
    const float* bf2  = (const float*)d_in[11];
    float* out = (float*)d_out;

    float *bufA, *bufB, *pool;
    cudaGetSymbolAddress((void**)&bufA, g_bufA);
    cudaGetSymbolAddress((void**)&bufB, g_bufB);
    cudaGetSymbolAddress((void**)&pool, g_pool);

    k_adj<<<ROWS * 32 / 256, 256>>>((const float4*)adj);         // ELL + dinv
    k_lin0<<<ROWS / 64, 256>>>(x, W1, bufA);                     // z0 -> A
    k_agg<1><<<NBLK, 128>>>(bufA, b1, W2, bufB);                 // layer1 -> B
    k_agg<1><<<NBLK, 128>>>(bufB, b2, W3, bufA);                 // layer2 -> A
    k_agg<0><<<NBLK, 128>>>(bufA, b3, nullptr, pool);            // layer3 -> pool
    k_final<<<BB, HEADD>>>(pool, Wf1, bf1, Wf2, bf2, out);       // head
}

// round 11
// speedup vs baseline: 1.7153x; 1.0616x over previous
#include <cuda_runtime.h>
#include <cstdint>

#define BB    32
#define NN    1024
#define ND    14
#define HID   64
#define HEADD 128
#define MAXN  64
#define ROWS  (BB*NN)          // 32768
#define RPB   32               // rows per block in agg kernels
#define NBLK  (ROWS/RPB)       // 1024
#define PAD   66               // padded h-row stride (floats)
#define WPAD  68               // padded W row stride (float4-aligned)

typedef unsigned long long ull;

#define ADD2(d, a, b) \
    asm("add.rn.f32x2 %0, %1, %2;" : "=l"(d) : "l"(a), "l"(b))
#define UNPACK2(lo, hi, s) \
    asm("mov.b64 {%0, %1}, %2;" : "=f"(lo), "=f"(hi) : "l"(s))

__device__ __forceinline__ uint32_t cvt_tf32(float x) {
    uint32_t r;
    asm("cvt.rna.tf32.f32 %0, %1;" : "=r"(r) : "f"(x));
    return r;
}

// ---------------- scratch (device globals; no allocations) ----------------
__device__ unsigned short g_nbr[ROWS * MAXN];   // ELL neighbor lists
__device__ int   g_cnt[ROWS];
__device__ float g_dinv[ROWS];
__device__ float g_bufA[ROWS * HID];
__device__ float g_bufB[ROWS * HID];
__device__ float g_pool[NBLK * HID];            // per-block pool partials

// ---------------------------------------------------------------------------
// K1: one warp per adjacency row; 8 float4 loads up-front, ballot-based
// nonzero extraction. uint16 ELL + dinv. 128MB read once -> HBM-bound.
// ---------------------------------------------------------------------------
__global__ void k_adj(const float4* __restrict__ adj4) {
    int gtid = blockIdx.x * blockDim.x + threadIdx.x;
    int row  = gtid >> 5;
    int lane = gtid & 31;
    if (row >= ROWS) return;

    const float4* rp = adj4 + (size_t)row * (NN / 4);
    float4 v[8];
    #pragma unroll
    for (int k = 0; k < 8; ++k) v[k] = rp[k * 32 + lane];

    int base = row * MAXN;
    unsigned lt = (1u << lane) - 1u;
    int cnt = 0;
    #pragma unroll
    for (int k = 0; k < 8; ++k) {
        int colb = (k * 32 + lane) * 4;
        bool px = v[k].x != 0.f, py = v[k].y != 0.f;
        bool pz = v[k].z != 0.f, pw = v[k].w != 0.f;
        unsigned b0 = __ballot_sync(0xffffffffu, px);
        unsigned b1 = __ballot_sync(0xffffffffu, py);
        unsigned b2 = __ballot_sync(0xffffffffu, pz);
        unsigned b3 = __ballot_sync(0xffffffffu, pw);
        int p0 = __popc(b0), p1 = __popc(b1), p2 = __popc(b2), p3 = __popc(b3);
        int o0 = cnt + __popc(b0 & lt);
        int o1 = cnt + p0 + __popc(b1 & lt);
        int o2 = cnt + p0 + p1 + __popc(b2 & lt);
        int o3 = cnt + p0 + p1 + p2 + __popc(b3 & lt);
        if (px && o0 < MAXN) g_nbr[base + o0] = (unsigned short)(colb);
        if (py && o1 < MAXN) g_nbr[base + o1] = (unsigned short)(colb + 1);
        if (pz && o2 < MAXN) g_nbr[base + o2] = (unsigned short)(colb + 2);
        if (pw && o3 < MAXN) g_nbr[base + o3] = (unsigned short)(colb + 3);
        cnt += p0 + p1 + p2 + p3;
    }
    if (lane == 0) {
        g_cnt[row]  = cnt;
        g_dinv[row] = rsqrtf((float)(cnt > 0 ? cnt : 1));
    }
}

// ---------------------------------------------------------------------------
// K2: z0[row] = dinv[row] * (x[row] @ W1). 64 rows / 256-thread block.
// ---------------------------------------------------------------------------
__global__ void __launch_bounds__(256) k_lin0(const float* __restrict__ x,
                                              const float* __restrict__ W1,
                                              float* __restrict__ out) {
    int tid = threadIdx.x;
    int g   = tid >> 6;
    int t   = tid & 63;
    int R0  = blockIdx.x * 64;

    __shared__ float sx[64 * ND];
    __shared__ float sdinv[64];

    float wreg[ND];
    #pragma unroll
    for (int c = 0; c < ND; ++c) wreg[c] = W1[c * HID + t];

    for (int i = tid; i < 64 * ND; i += 256) sx[i] = x[(size_t)R0 * ND + i];
    if (tid < 64) sdinv[tid] = g_dinv[R0 + tid];
    __syncthreads();

    #pragma unroll 4
    for (int rr = 0; rr < 16; ++rr) {
        int r = g * 16 + rr;
        const float* xr = sx + r * ND;
        float a = 0.f;
        #pragma unroll
        for (int c = 0; c < ND; ++c) a = fmaf(xr[c], wreg[c], a);
        out[(size_t)(R0 + r) * HID + t] = a * sdinv[r];
    }
}

// ---------------------------------------------------------------------------
// K3: fused aggregation layer, 32 rows / 128-thread block (grid 1024).
//  Phase 1: warp w = rows w*8..w*8+7 interleaved; lane = channel pair;
//           SOFTWARE-PIPELINED gather (round k+1 loads in flight while
//           accumulating round k; off-rows load 0 so adds are unconditional).
//  Phase 2 (HAS_MV): 32x64x64 GEMM via tf32 mma.sync.m16n8k8.
// ---------------------------------------------------------------------------
template <int HAS_MV>
__global__ void __launch_bounds__(128) k_agg(const float* __restrict__ zin,
                                             const float* __restrict__ bias,
                                             const float* __restrict__ Wnext,
                                             float* __restrict__ out) {
    int tid  = threadIdx.x;
    int w    = tid >> 5;
    int lane = tid & 31;
    int R0   = blockIdx.x * RPB;
    int bbase = (R0 >> 10) << 10;                 // batch * N

    __shared__ unsigned short sidx[RPB * MAXN];   // 4 KB
    __shared__ float sh[HAS_MV ? RPB * PAD : 1];  // 8.25 KB
    __shared__ float sW[HAS_MV ? HID * WPAD : 1]; // 17 KB (padded rows)
    __shared__ float sdinv[RPB];
    __shared__ int   scnt[RPB];
    __shared__ float2 spart[4][32];

    // ---- stage: ELL lists (int4), W (padded float4), dinv, cnt ----
    {
        const int4* src = (const int4*)(g_nbr + (size_t)R0 * MAXN);
        int4* dst = (int4*)sidx;
        dst[tid]       = src[tid];
        dst[tid + 128] = src[tid + 128];
        if (HAS_MV) {
            const float4* ws = (const float4*)Wnext;
            #pragma unroll
            for (int i = 0; i < 8; ++i) {
                int f   = tid + i * 128;          // 0..1023
                float4 v = ws[f];
                int row = f >> 4;
                int c4  = f & 15;
                *(float4*)(sW + row * WPAD + c4 * 4) = v;
            }
        }
        if (tid < RPB) {
            int c = g_cnt[R0 + tid];
            scnt[tid]  = c > MAXN ? MAXN : c;
            sdinv[tid] = g_dinv[R0 + tid];
        }
    }
    __syncthreads();

    // ---- phase 1: pipelined interleaved gather ----
    {
        const float2 bf = ((const float2*)bias)[lane];
        const ull* zb = (const ull*)zin + (size_t)bbase * (HID / 2) + lane;

        int r0 = w * 8;
        int cn[8];
        const unsigned short* ip[8];
        ull acc[8], v[8];
        #pragma unroll
        for (int i = 0; i < 8; ++i) {
            cn[i]  = scnt[r0 + i];
            ip[i]  = sidx + (r0 + i) * MAXN;
            acc[i] = 0ull;
        }
        int cmax = 0;
        #pragma unroll
        for (int i = 0; i < 8; ++i) cmax = max(cmax, cn[i]);

        // prologue: round 0 loads (0 if row is done)
        #pragma unroll
        for (int i = 0; i < 8; ++i)
            v[i] = (0 < cn[i]) ? zb[ip[i][0] * (HID / 2)] : 0ull;

        #pragma unroll 2
        for (int k = 0; k < cmax; ++k) {
            ull vn[8];
            #pragma unroll
            for (int i = 0; i < 8; ++i)
                vn[i] = (k + 1 < cn[i]) ? zb[ip[i][k + 1] * (HID / 2)] : 0ull;
            #pragma unroll
            for (int i = 0; i < 8; ++i)
                ADD2(acc[i], acc[i], v[i]);
            #pragma unroll
            for (int i = 0; i < 8; ++i)
                v[i] = vn[i];
        }

        float2 pacc = make_float2(0.f, 0.f);
        #pragma unroll
        for (int i = 0; i < 8; ++i) {
            float ax, ay;
            UNPACK2(ax, ay, acc[i]);
            float di = sdinv[r0 + i];
            float hx = fmaxf(fmaf(di, ax, bf.x), 0.f);
            float hy = fmaxf(fmaf(di, ay, bf.y), 0.f);
            if (HAS_MV) {
                *(float2*)(sh + (r0 + i) * PAD + 2 * lane) = make_float2(hx, hy);
            } else {
                pacc.x += hx; pacc.y += hy;
            }
        }

        if (!HAS_MV) {
            spart[w][lane] = pacc;
            __syncthreads();
            if (tid < 32) {
                float2 s = spart[0][tid];
                #pragma unroll
                for (int i = 1; i < 4; ++i) { s.x += spart[i][tid].x; s.y += spart[i][tid].y; }
                *(float2*)(out + blockIdx.x * HID + 2 * tid) = s;
            }
            return;
        }
    }

    __syncthreads();

    // ---- phase 2: 32x64x64 GEMM via tf32 HMMA ----
    {
        int g  = lane >> 2;                 // 0..7
        int tg = lane & 3;                  // 0..3
        int mrow = (w & 1) * 16;            // 0 or 16
        int ncol = (w >> 1) * 32;           // 0 or 32

        float c[4][4];
        #pragma unroll
        for (int j = 0; j < 4; ++j)
            #pragma unroll
            for (int i = 0; i < 4; ++i) c[j][i] = 0.f;

        #pragma unroll
        for (int k0 = 0; k0 < HID; k0 += 8) {
            uint32_t a[4];
            a[0] = cvt_tf32(sh[(mrow + g    ) * PAD + k0 + tg]);
            a[1] = cvt_tf32(sh[(mrow + g + 8) * PAD + k0 + tg]);
            a[2] = cvt_tf32(sh[(mrow + g    ) * PAD + k0 + tg + 4]);
            a[3] = cvt_tf32(sh[(mrow + g + 8) * PAD + k0 + tg + 4]);
            #pragma unroll
            for (int j = 0; j < 4; ++j) {
                int n0 = ncol + j * 8;
                uint32_t b[2];
                b[0] = cvt_tf32(sW[(k0 + tg    ) * WPAD + n0 + g]);
                b[1] = cvt_tf32(sW[(k0 + tg + 4) * WPAD + n0 + g]);
                asm volatile(
                    "mma.sync.aligned.m16n8k8.row.col.f32.tf32.tf32.f32 "
                    "{%0,%1,%2,%3},{%4,%5,%6,%7},{%8,%9},{%0,%1,%2,%3};"
                    : "+f"(c[j][0]), "+f"(c[j][1]), "+f"(c[j][2]), "+f"(c[j][3])
                    : "r"(a[0]), "r"(a[1]), "r"(a[2]), "r"(a[3]),
                      "r"(b[0]), "r"(b[1]));
            }
        }

        int r0 = mrow + g, r1 = mrow + g + 8;
        float d0 = sdinv[r0], d1 = sdinv[r1];
        #pragma unroll
        for (int j = 0; j < 4; ++j) {
            int n0 = ncol + j * 8 + 2 * tg;
            *(float2*)(out + (size_t)(R0 + r0) * HID + n0) =
                make_float2(d0 * c[j][0], d0 * c[j][1]);
            *(float2*)(out + (size_t)(R0 + r1) * HID + n0) =
                make_float2(d1 * c[j][2], d1 * c[j][3]);
        }
    }
}

// ---------------------------------------------------------------------------
// K4: per batch: pooled = mean of 32 block partials; relu(pooled@Wf1+bf1)@Wf2+bf2
// ---------------------------------------------------------------------------
__global__ void k_final(const float* __restrict__ pool,
                        const float* __restrict__ Wf1, const float* __restrict__ bf1,
                        const float* __restrict__ Wf2, const float* __restrict__ bf2,
                        float* __restrict__ out) {
    int b   = blockIdx.x;
    int tid = threadIdx.x;           // 128 threads
    __shared__ float pooled[HID];
    __shared__ float hred[HEADD];

    if (tid < HID) {
        float s = 0.f;
        #pragma unroll
        for (int i = 0; i < NN / RPB; ++i)
            s += pool[(b * (NN / RPB) + i) * HID + tid];
        pooled[tid] = s * (1.f / NN);
    }
    __syncthreads();

    float a = bf1[tid];
    #pragma unroll
    for (int c = 0; c < HID; ++c) a = fmaf(pooled[c], Wf1[c * HEADD + tid], a);
    hred[tid] = fmaxf(a, 0.f) * Wf2[tid];
    __syncthreads();

    if (tid < 32) {
        float s = hred[tid] + hred[tid + 32] + hred[tid + 64] + hred[tid + 96];
        #pragma unroll
        for (int d = 16; d; d >>= 1) s += __shfl_down_sync(0xffffffffu, s, d);
        if (tid == 0) out[b] = s + bf2[0];
    }
}

// ---------------------------------------------------------------------------
extern "C" void kernel_launch(void* const* d_in, const int* in_sizes, int n_in,
                              void* d_out, int out_size) {
    const float* x    = (const float*)d_in[0];
    const float* adj  = (const float*)d_in[1];
    const float* W1   = (const float*)d_in[2];
    const float* b1   = (const float*)d_in[3];
    const float* W2   = (const float*)d_in[4];
    const float* b2   = (const float*)d_in[5];
    const float* W3   = (const float*)d_in[6];
    const float* b3   = (const float*)d_in[7];
    const float* Wf1  = (const float*)d_in[8];
    const float* bf1  = (const float*)d_in[9];
    const float* Wf2  = (const float*)d_in[10];
    const float* bf2  = (const float*)d_in[11];
    float* out = (float*)d_out;

    float *bufA, *bufB, *pool;
    cudaGetSymbolAddress((void**)&bufA, g_bufA);
    cudaGetSymbolAddress((void**)&bufB, g_bufB);
    cudaGetSymbolAddress((void**)&pool, g_pool);

    k_adj<<<ROWS * 32 / 256, 256>>>((const float4*)adj);         // ELL + dinv
    k_lin0<<<ROWS / 64, 256>>>(x, W1, bufA);                     // z0 -> A
    k_agg<1><<<NBLK, 128>>>(bufA, b1, W2, bufB);                 // layer1 -> B
    k_agg<1><<<NBLK, 128>>>(bufB, b2, W3, bufA);                 // layer2 -> A
    k_agg<0><<<NBLK, 128>>>(bufA, b3, nullptr, pool);            // layer3 -> pool
    k_final<<<BB, HEADD>>>(pool, Wf1, bf1, Wf2, bf2, out);       // head
}